// round 3
// baseline (speedup 1.0000x reference)
#include <cuda_runtime.h>
#include <mma.h>

using namespace nvcuda;

#define BATCH 4
#define HEADS 12
#define SEQ   2048
#define DK    64
#define TQ    64
#define TK    64
#define LD    72   // smem row pitch (floats): 16B-aligned, 72 mod 32 = 8 to spread banks

__device__ __forceinline__ float to_tf32(float x) {
    asm volatile("cvt.rna.tf32.f32 %0, %0;" : "+f"(x));
    return x;
}

__global__ void __launch_bounds__(256)
attn_kernel(const float* __restrict__ Q, const float* __restrict__ K,
            const float* __restrict__ V, const float* __restrict__ M,
            float* __restrict__ ctx_out, float* __restrict__ attn_out)
{
    extern __shared__ float sm[];
    float* Qs    = sm;               // TQ x LD   (Q tile, tf32-rounded)
    float* KVs   = sm + TQ * LD;     // TK x LD   (K tile, then V tile)
    float* Es    = sm + 2 * TQ * LD; // TQ x LD   (scores -> e -> ctx staging)
    float* inv_s = sm + 3 * TQ * LD; // TQ

    const int qt = blockIdx.x, h = blockIdx.y, b = blockIdx.z;
    const int tid  = threadIdx.x;
    const int warp = tid >> 5;

    const size_t bh = (size_t)b * HEADS + h;
    const float* Qb = Q + (bh * SEQ + (size_t)qt * TQ) * DK;
    const float* Kb = K + bh * SEQ * DK;
    const float* Vb = V + bh * SEQ * DK;
    const float* Mb = M + ((size_t)b * SEQ + (size_t)qt * TQ) * SEQ;
    float* Ab = attn_out + (bh * SEQ + (size_t)qt * TQ) * SEQ;
    float* Cb = ctx_out  + (bh * SEQ + (size_t)qt * TQ) * DK;

    // ---- load Q tile (tf32-rounded once) ----
    for (int i = tid; i < TQ * 16; i += 256) {
        int r = i >> 4, c = (i & 15) << 2;
        float4 v = *(const float4*)(Qb + (size_t)r * DK + c);
        Qs[r * LD + c + 0] = to_tf32(v.x);
        Qs[r * LD + c + 1] = to_tf32(v.y);
        Qs[r * LD + c + 2] = to_tf32(v.z);
        Qs[r * LD + c + 3] = to_tf32(v.w);
    }

    const int rowblk = warp >> 1;   // 0..3 : rows rowblk*16
    const int colblk = warp & 1;    // 0..1 : cols colblk*32 (+0, +16)

    wmma::fragment<wmma::accumulator, 16, 16, 8, float> c0, c1;
    wmma::fill_fragment(c0, 0.f);
    wmma::fill_fragment(c1, 0.f);

    const int myrow = tid >> 2;     // 0..63
    const int cq    = tid & 3;      // 16-col quarter
    float rsum = 0.f;

    for (int kt = 0; kt < SEQ / TK; ++kt) {
        __syncthreads();  // (A) prev-iter ctx MMA done before KVs/Es reuse

        // ---- load K tile ----
        for (int i = tid; i < TK * 16; i += 256) {
            int r = i >> 4, c = (i & 15) << 2;
            float4 v = *(const float4*)(Kb + ((size_t)kt * TK + r) * DK + c);
            KVs[r * LD + c + 0] = to_tf32(v.x);
            KVs[r * LD + c + 1] = to_tf32(v.y);
            KVs[r * LD + c + 2] = to_tf32(v.z);
            KVs[r * LD + c + 3] = to_tf32(v.w);
        }
        __syncthreads();  // (B)

        // ---- scores = Q . K^T (tf32) ----
        wmma::fragment<wmma::accumulator, 16, 16, 8, float> s0, s1;
        wmma::fill_fragment(s0, 0.f);
        wmma::fill_fragment(s1, 0.f);
        #pragma unroll
        for (int kk = 0; kk < DK; kk += 8) {
            wmma::fragment<wmma::matrix_a, 16, 16, 8, wmma::precision::tf32, wmma::row_major> a;
            wmma::load_matrix_sync(a, &Qs[rowblk * 16 * LD + kk], LD);
            wmma::fragment<wmma::matrix_b, 16, 16, 8, wmma::precision::tf32, wmma::col_major> b0, b1;
            wmma::load_matrix_sync(b0, &KVs[(colblk * 32 +  0) * LD + kk], LD);
            wmma::load_matrix_sync(b1, &KVs[(colblk * 32 + 16) * LD + kk], LD);
            wmma::mma_sync(s0, a, b0, s0);
            wmma::mma_sync(s1, a, b1, s1);
        }
        wmma::store_matrix_sync(&Es[rowblk * 16 * LD + colblk * 32 +  0], s0, LD, wmma::mem_row_major);
        wmma::store_matrix_sync(&Es[rowblk * 16 * LD + colblk * 32 + 16], s1, LD, wmma::mem_row_major);
        __syncthreads();  // (C) scores visible

        // ---- elementwise: e = exp(s/8)*mask; write attn (unnorm); rowsum; tf32(e)->Es ----
        {
            const float* mrow = Mb + (size_t)myrow * SEQ + kt * TK + cq * 16;
            float*       arow = Ab + (size_t)myrow * SEQ + kt * TK + cq * 16;
            float*       erow = &Es[myrow * LD + cq * 16];
            #pragma unroll
            for (int j = 0; j < 4; ++j) {
                float4 m = *(const float4*)(mrow + j * 4);
                float e0 = __expf(erow[j * 4 + 0] * 0.125f) * m.x;
                float e1 = __expf(erow[j * 4 + 1] * 0.125f) * m.y;
                float e2 = __expf(erow[j * 4 + 2] * 0.125f) * m.z;
                float e3 = __expf(erow[j * 4 + 3] * 0.125f) * m.w;
                *(float4*)(arow + j * 4) = make_float4(e0, e1, e2, e3);
                rsum += (e0 + e1) + (e2 + e3);
                erow[j * 4 + 0] = to_tf32(e0);
                erow[j * 4 + 1] = to_tf32(e1);
                erow[j * 4 + 2] = to_tf32(e2);
                erow[j * 4 + 3] = to_tf32(e3);
            }
        }

        // ---- load V tile (KVs safe: score MMA finished before sync C) ----
        for (int i = tid; i < TK * 16; i += 256) {
            int r = i >> 4, c = (i & 15) << 2;
            float4 v = *(const float4*)(Vb + ((size_t)kt * TK + r) * DK + c);
            KVs[r * LD + c + 0] = to_tf32(v.x);
            KVs[r * LD + c + 1] = to_tf32(v.y);
            KVs[r * LD + c + 2] = to_tf32(v.z);
            KVs[r * LD + c + 3] = to_tf32(v.w);
        }
        __syncthreads();  // (D) e + V ready

        // ---- ctx += E . V (tf32) ----
        #pragma unroll
        for (int kk = 0; kk < TK; kk += 8) {
            wmma::fragment<wmma::matrix_a, 16, 16, 8, wmma::precision::tf32, wmma::row_major> a;
            wmma::load_matrix_sync(a, &Es[rowblk * 16 * LD + kk], LD);
            wmma::fragment<wmma::matrix_b, 16, 16, 8, wmma::precision::tf32, wmma::row_major> v0, v1;
            wmma::load_matrix_sync(v0, &KVs[kk * LD + colblk * 32 +  0], LD);
            wmma::load_matrix_sync(v1, &KVs[kk * LD + colblk * 32 + 16], LD);
            wmma::mma_sync(c0, a, v0, c0);
            wmma::mma_sync(c1, a, v1, c1);
        }
    }

    // ---- rowsum reduce: 4 consecutive lanes own one row ----
    rsum += __shfl_xor_sync(0xffffffffu, rsum, 1);
    rsum += __shfl_xor_sync(0xffffffffu, rsum, 2);
    if (cq == 0) inv_s[myrow] = 1.f / (rsum + 1e-8f);
    __syncthreads();  // last ctx MMA read of Es done; inv_s visible

    wmma::store_matrix_sync(&Es[rowblk * 16 * LD + colblk * 32 +  0], c0, LD, wmma::mem_row_major);
    wmma::store_matrix_sync(&Es[rowblk * 16 * LD + colblk * 32 + 16], c1, LD, wmma::mem_row_major);
    __syncthreads();

    // ---- write normalized context ----
    {
        float inv = inv_s[myrow];
        float* crow = Cb + (size_t)myrow * DK + cq * 16;
        float* erow = &Es[myrow * LD + cq * 16];
        #pragma unroll
        for (int j = 0; j < 4; ++j) {
            *(float4*)(crow + j * 4) = make_float4(erow[j * 4 + 0] * inv, erow[j * 4 + 1] * inv,
                                                   erow[j * 4 + 2] * inv, erow[j * 4 + 3] * inv);
        }
    }

    // ---- normalize attn strip in place (coalesced float4, mostly L2-hot) ----
    for (int ii = tid; ii < TQ * (SEQ / 4); ii += 256) {
        int r  = ii >> 9;            // SEQ/4 = 512 float4 per row
        int c4 = (ii & 511) << 2;
        float inv = inv_s[r];
        float4 v = *(float4*)(Ab + (size_t)r * SEQ + c4);
        v.x *= inv; v.y *= inv; v.z *= inv; v.w *= inv;
        *(float4*)(Ab + (size_t)r * SEQ + c4) = v;
    }
}

extern "C" void kernel_launch(void* const* d_in, const int* in_sizes, int n_in,
                              void* d_out, int out_size)
{
    const float* Q = (const float*)d_in[0];
    const float* K = (const float*)d_in[1];
    const float* V = (const float*)d_in[2];
    const float* M = (const float*)d_in[3];

    float* ctx  = (float*)d_out;                                  // B*H*S*DK
    float* attn = (float*)d_out + (size_t)BATCH * HEADS * SEQ * DK; // B*H*S*S

    const size_t smem = (size_t)(3 * TQ * LD + TQ) * sizeof(float); // 55552 B
    cudaFuncSetAttribute(attn_kernel, cudaFuncAttributeMaxDynamicSharedMemorySize, (int)smem);

    dim3 grid(SEQ / TQ, HEADS, BATCH);
    attn_kernel<<<grid, 256, smem>>>(Q, K, V, M, ctx, attn);
}